// round 7
// baseline (speedup 1.0000x reference)
#include <cuda_runtime.h>
#include <cuda_bf16.h>
#include <cstdint>

// ---------------- problem-size scratch (static device globals; no allocs) ---
#define NMAX 100096
#define EMAX 1600256
#define ENMAX (NMAX + EMAX)
#define POOLB 240

__device__ int    g_not64;               // 1 if edge_index is int32
__device__ int    g_deg[NMAX];
__device__ int    g_rp[NMAX + 1];
__device__ int    g_cur[NMAX];
__device__ int    g_bsum[128];
__device__ int    g_ss[ENMAX];           // src per CSR slot
__device__ int    g_sd[ENMAX];           // dst per CSR slot
__device__ float  g_w[ENMAX];            // softmax weight per CSR slot
__device__ float2 g_h1[NMAX * 32];       // layer1 features, interleaved (c, c+32)
__device__ float  g_g1[NMAX * 64];       // layer1 output (post relu) = layer2 input
__device__ float2 g_h2[NMAX * 32];       // layer2 features, interleaved
__device__ float  g_g2[NMAX * 64];       // layer2 output
__device__ float  g_as1[NMAX], g_ad1[NMAX];
__device__ float  g_as2[NMAX], g_ad2[NMAX];
__device__ float  g_pool[POOLB * 64];    // pool partials
__device__ float  g_dummy[NMAX * 64];    // probe / duplicate-launch sink

// ---------------- init ------------------------------------------------------
__global__ void k_zero(int n) {
    int i = blockIdx.x * blockDim.x + threadIdx.x;
    if (i < n) g_deg[i] = 0;
    if (i == 0) g_not64 = 0;
}

// ---------------- edge-index dtype detection --------------------------------
__global__ void k_detect(const long long* __restrict__ ei, int nq) {
    int i = blockIdx.x * blockDim.x + threadIdx.x;
    if (i < nq && ((unsigned long long)ei[i] >> 32) != 0ull) atomicOr(&g_not64, 1);
}

__device__ __forceinline__ int load_idx(const void* ei, long long pos) {
    if (g_not64) return ((const int*)ei)[pos];
    return (int)((const long long*)ei)[pos];
}

__device__ __forceinline__ int clampi(int v, int n) {
    v = v < 0 ? 0 : v;
    return v >= n ? n - 1 : v;
}

// ---------------- degree histogram (incl. self loops) -----------------------
__global__ void k_hist(const void* __restrict__ ei, int E, int EN, int n) {
    int i = blockIdx.x * blockDim.x + threadIdx.x;
    if (i >= EN) return;
    int d = (i < E) ? clampi(load_idx(ei, (long long)E + i), n) : (i - E);
    atomicAdd(&g_deg[d], 1);
}

// ---------------- SYNTHETIC GATHER PROBE -------------------------------------
// Exactly k_agg2's memory pattern: warp per node, 16 edges, 4-deep unrolled
// 256B H-row gathers + coalesced w reads. Indices are hash-computed (no CSR
// dependency) so the profiled launch measures the true gather roofline.
__global__ void __launch_bounds__(256)
k_probe(const float2* __restrict__ H, float* __restrict__ OUT, int n) {
    int gw = (blockIdx.x * blockDim.x + threadIdx.x) >> 5;
    int lane = threadIdx.x & 31;
    if (gw >= n) return;

    unsigned st = (unsigned)gw * 2654435761u + 12345u;
    int jb = (gw & 8191) * 16;          // fake CSR row into g_w

    float den = 0.f;
    if (lane < 16) den = g_w[jb + lane];
#pragma unroll
    for (int o = 16; o; o >>= 1) den += __shfl_xor_sync(0xffffffffu, den, o);

    float acc0 = 0.f, acc1 = 0.f;
#pragma unroll
    for (int t = 0; t < 4; t++) {
        unsigned b = st + (unsigned)t * 0x9E3779B9u;
        unsigned r0 = b * 0x85EBCA6Bu;  r0 ^= r0 >> 13;
        unsigned r1 = b * 0xC2B2AE35u;  r1 ^= r1 >> 11;
        unsigned r2 = b * 0x27D4EB2Fu;  r2 ^= r2 >> 15;
        unsigned r3 = b * 0x165667B1u;  r3 ^= r3 >> 14;
        int s0 = (int)(r0 % (unsigned)n);
        int s1 = (int)(r1 % (unsigned)n);
        int s2 = (int)(r2 % (unsigned)n);
        int s3 = (int)(r3 % (unsigned)n);
        float w0 = g_w[jb + t * 4 + 0], w1 = g_w[jb + t * 4 + 1];
        float w2 = g_w[jb + t * 4 + 2], w3 = g_w[jb + t * 4 + 3];
        float2 h0 = H[(size_t)s0 * 32 + lane];
        float2 h1 = H[(size_t)s1 * 32 + lane];
        float2 h2 = H[(size_t)s2 * 32 + lane];
        float2 h3 = H[(size_t)s3 * 32 + lane];
        acc0 += w0 * h0.x + w1 * h1.x + w2 * h2.x + w3 * h3.x;
        acc1 += w0 * h0.y + w1 * h1.y + w2 * h2.y + w3 * h3.y;
    }
    size_t o = (size_t)gw * 64;
    OUT[o + lane] = acc0 + den;
    OUT[o + 32 + lane] = acc1;
}

// ---------------- prefix scan -------------------------------------------------
__global__ void k_scan_block(int n) {
    __shared__ int s[1024];
    int i = blockIdx.x * 1024 + threadIdx.x;
    int v = (i < n) ? g_deg[i] : 0;
    s[threadIdx.x] = v;
    __syncthreads();
#pragma unroll
    for (int o = 1; o < 1024; o <<= 1) {
        int t = (threadIdx.x >= (unsigned)o) ? s[threadIdx.x - o] : 0;
        __syncthreads();
        s[threadIdx.x] += t;
        __syncthreads();
    }
    if (i < n) g_rp[i] = s[threadIdx.x] - v;          // exclusive within block
    if (threadIdx.x == 1023) g_bsum[blockIdx.x] = s[1023];
}

__global__ void k_scan_top(int nb) {      // one block, 128 threads, nb <= 128
    __shared__ int s[128];
    int t = threadIdx.x;
    int v = (t < nb) ? g_bsum[t] : 0;
    s[t] = v;
    __syncthreads();
#pragma unroll
    for (int o = 1; o < 128; o <<= 1) {
        int tv = (t >= (unsigned)o) ? s[t - o] : 0;
        __syncthreads();
        s[t] += tv;
        __syncthreads();
    }
    if (t < nb) g_bsum[t] = s[t] - v;                 // exclusive
}

__global__ void k_scan_add(int n, int total) {
    int i = blockIdx.x * blockDim.x + threadIdx.x;
    if (i < n) {
        int v = g_rp[i] + g_bsum[i >> 10];
        g_rp[i] = v;
        g_cur[i] = v;
    }
    if (i == 0) g_rp[n] = total;
}

// ---------------- scatter edges into CSR order (src + dst per slot) ---------
__global__ void k_scatter(const void* __restrict__ ei, int E, int EN, int n) {
    int i = blockIdx.x * blockDim.x + threadIdx.x;
    if (i >= EN) return;
    int s, d;
    if (i < E) {
        s = clampi(load_idx(ei, i), n);
        d = clampi(load_idx(ei, (long long)E + i), n);
    } else { s = i - E; d = s; }
    int pos = atomicAdd(&g_cur[d], 1);
    if (pos >= 0 && pos < ENMAX) { g_ss[pos] = s; g_sd[pos] = d; }
}

// ---------------- GEMM + attention scalars ----------------------------------
// 256 threads, 8 warps, 2 node-rows per warp (16 rows/block).
template <int FIN>
__global__ void __launch_bounds__(256)
k_gemm(const float* __restrict__ X, const float* __restrict__ Wg,
       const float* __restrict__ att_s, const float* __restrict__ att_d,
       float2* __restrict__ H, float* __restrict__ AS, float* __restrict__ AD,
       int n) {
    __shared__ float2 Wp[FIN * 32];
    __shared__ float atts[64], attd[64];
    __shared__ __align__(16) float xs[8][2][FIN];

    int tid = threadIdx.x;
    for (int i = tid; i < FIN * 32; i += 256) {
        int k = i >> 5, c = i & 31;
        Wp[i] = make_float2(Wg[k * 64 + c], Wg[k * 64 + c + 32]);
    }
    if (tid < 64) { atts[tid] = att_s[tid]; attd[tid] = att_d[tid]; }
    __syncthreads();

    int warp = tid >> 5, lane = tid & 31;
    int stride = gridDim.x * 16;

    for (int base = (blockIdx.x * 8 + warp) * 2; base < n; base += stride) {
        int nrows = n - base;
        if (nrows > 2) nrows = 2;
        for (int r = 0; r < nrows; r++) {
            const float* xp = X + (size_t)(base + r) * FIN;
#pragma unroll
            for (int k = lane; k < FIN; k += 32) xs[warp][r][k] = xp[k];
        }
        __syncwarp();

        float a00 = 0.f, a01 = 0.f, a10 = 0.f, a11 = 0.f;
#pragma unroll
        for (int k4 = 0; k4 < FIN; k4 += 4) {
            float4 x0 = *(const float4*)&xs[warp][0][k4];
            float4 x1 = *(const float4*)&xs[warp][1][k4];
#pragma unroll
            for (int kk = 0; kk < 4; kk++) {
                float2 w = Wp[(k4 + kk) * 32 + lane];
                float x0k = (kk == 0) ? x0.x : (kk == 1) ? x0.y : (kk == 2) ? x0.z : x0.w;
                float x1k = (kk == 0) ? x1.x : (kk == 1) ? x1.y : (kk == 2) ? x1.z : x1.w;
                a00 += x0k * w.x; a01 += x0k * w.y;
                a10 += x1k * w.x; a11 += x1k * w.y;
            }
        }

#pragma unroll
        for (int r = 0; r < 2; r++) {
            if (r >= nrows) break;
            float v0 = r ? a10 : a00, v1 = r ? a11 : a01;
            H[(size_t)(base + r) * 32 + lane] = make_float2(v0, v1);
            float ps = v0 * atts[lane] + v1 * atts[lane + 32];
            float pd = v0 * attd[lane] + v1 * attd[lane + 32];
#pragma unroll
            for (int ofs = 16; ofs; ofs >>= 1) {
                ps += __shfl_xor_sync(0xffffffffu, ps, ofs);
                pd += __shfl_xor_sync(0xffffffffu, pd, ofs);
            }
            if (lane == 0) { AS[base + r] = ps; AD[base + r] = pd; }
        }
        __syncwarp();
    }
}

// ---------------- edge weights (edge-parallel, CSR-slot order) ---------------
__global__ void k_edgew(const float* __restrict__ AS, const float* __restrict__ AD,
                        int EN) {
    int j = blockIdx.x * blockDim.x + threadIdx.x;
    if (j >= EN) return;
    float e = AS[g_ss[j]] + AD[g_sd[j]];
    e = (e > 0.f) ? e : 0.2f * e;            // leaky_relu, slope 0.2
    g_w[j] = __expf(e);
}

// ---------------- aggregation: warp per node, 4-deep pipelined gather --------
__global__ void __launch_bounds__(256)
k_agg2(const float2* __restrict__ H, const float* __restrict__ bias,
       float* __restrict__ OUT, int n, int do_relu) {
    int gw = (blockIdx.x * blockDim.x + threadIdx.x) >> 5;
    int lane = threadIdx.x & 31;
    if (gw >= n) return;

    int beg = g_rp[gw], end = g_rp[gw + 1];

    // denominator: lane-parallel over contiguous w row
    float den = 0.f;
    for (int jj = beg + lane; jj < end; jj += 32) den += g_w[jj];
#pragma unroll
    for (int o = 16; o; o >>= 1) den += __shfl_xor_sync(0xffffffffu, den, o);

    // numerator: 4 independent H gathers in flight
    float acc0 = 0.f, acc1 = 0.f;
    int j = beg;
    for (; j + 4 <= end; j += 4) {
        int s0 = g_ss[j], s1 = g_ss[j + 1], s2 = g_ss[j + 2], s3 = g_ss[j + 3];
        float w0 = g_w[j], w1 = g_w[j + 1], w2 = g_w[j + 2], w3 = g_w[j + 3];
        float2 h0 = H[(size_t)s0 * 32 + lane];
        float2 h1 = H[(size_t)s1 * 32 + lane];
        float2 h2 = H[(size_t)s2 * 32 + lane];
        float2 h3 = H[(size_t)s3 * 32 + lane];
        acc0 += w0 * h0.x + w1 * h1.x + w2 * h2.x + w3 * h3.x;
        acc1 += w0 * h0.y + w1 * h1.y + w2 * h2.y + w3 * h3.y;
    }
    for (; j < end; j++) {
        int s = g_ss[j];
        float w = g_w[j];
        float2 hv = H[(size_t)s * 32 + lane];
        acc0 += w * hv.x;
        acc1 += w * hv.y;
    }

    float inv = 1.f / (den + 1e-16f);
    float v0 = fmaf(acc0, inv, bias[lane]);
    float v1 = fmaf(acc1, inv, bias[lane + 32]);
    if (do_relu) { v0 = fmaxf(v0, 0.f); v1 = fmaxf(v1, 0.f); }
    size_t o = (size_t)gw * 64;
    OUT[o + lane] = v0;
    OUT[o + 32 + lane] = v1;
}

// ---------------- global mean pool (atomic-free, 2 stages) -------------------
__global__ void k_pool_a(const float* __restrict__ G, int n) {
    __shared__ float sm[256];
    int col = threadIdx.x & 63;
    int rg = threadIdx.x >> 6;   // 0..3
    float acc = 0.f;
    for (int r = blockIdx.x * 4 + rg; r < n; r += gridDim.x * 4)
        acc += G[(size_t)r * 64 + col];
    sm[threadIdx.x] = acc;
    __syncthreads();
    if (rg == 0)
        g_pool[blockIdx.x * 64 + col] =
            sm[col] + sm[64 + col] + sm[128 + col] + sm[192 + col];
}

__global__ void k_pool_b(float* __restrict__ out, int n) {
    int col = threadIdx.x;   // 64 threads
    float acc = 0.f;
    for (int b = 0; b < POOLB; b++) acc += g_pool[b * 64 + col];
    out[col] = acc * (1.0f / (float)n);
}

// ---------------- launch ----------------------------------------------------
extern "C" void kernel_launch(void* const* d_in, const int* in_sizes, int n_in,
                              void* d_out, int out_size) {
    const float* x   = (const float*)d_in[0];
    const void*  ei  = d_in[1];   // edge_index, dtype detected on device
    const float* W1  = (const float*)d_in[3];
    const float* as1 = (const float*)d_in[4];
    const float* ad1 = (const float*)d_in[5];
    const float* b1  = (const float*)d_in[6];
    const float* W2  = (const float*)d_in[7];
    const float* as2 = (const float*)d_in[8];
    const float* ad2 = (const float*)d_in[9];
    const float* b2  = (const float*)d_in[10];
    float* out = (float*)d_out;

    int n  = in_sizes[0] / 128;   // N nodes
    int E  = in_sizes[1] / 2;     // edges
    int EN = E + n;               // edges + self loops

    int gemmBlocks = (n + 15) / 16;
    int aggBlocks  = (n + 7) / 8;

    k_zero<<<(n + 255) / 256, 256>>>(n);                               // 0
    int nq = E < 2048 ? E : 2048;
    k_detect<<<(nq + 255) / 256, 256>>>((const long long*)ei, nq);     // 1
    k_hist<<<(EN + 255) / 256, 256>>>(ei, E, EN, n);                   // 2
    // PROBE at profiled slot 3: synthetic gather, k_agg2's exact pattern.
    k_probe<<<aggBlocks, 256>>>(g_h1, g_dummy, n);                     // 3 <- profiled
    int nb = (n + 1023) / 1024;
    k_scan_block<<<nb, 1024>>>(n);                                     // 4
    k_scan_top<<<1, 128>>>(nb);                                        // 5
    k_scan_add<<<(n + 255) / 256, 256>>>(n, EN);                       // 6
    k_scatter<<<(EN + 255) / 256, 256>>>(ei, E, EN, n);                // 7

    // --- layer 1 ---
    k_gemm<128><<<gemmBlocks, 256>>>(x, W1, as1, ad1, g_h1, g_as1, g_ad1, n);
    k_edgew<<<(EN + 255) / 256, 256>>>(g_as1, g_ad1, EN);
    k_agg2<<<aggBlocks, 256>>>(g_h1, b1, g_g1, n, 1);
    // DUPLICATE real agg2 into dummy: total-time delta measures agg2 cost.
    k_agg2<<<aggBlocks, 256>>>(g_h1, b1, g_dummy, n, 1);

    // --- layer 2 ---
    k_gemm<64><<<gemmBlocks, 256>>>(g_g1, W2, as2, ad2, g_h2, g_as2, g_ad2, n);
    k_edgew<<<(EN + 255) / 256, 256>>>(g_as2, g_ad2, EN);
    k_agg2<<<aggBlocks, 256>>>(g_h2, b2, g_g2, n, 0);

    // --- global mean pool (atomic-free) ---
    k_pool_a<<<POOLB, 256>>>(g_g2, n);
    k_pool_b<<<1, 64>>>(out, n);
}

// round 8
// speedup vs baseline: 6.1788x; 6.1788x over previous
#include <cuda_runtime.h>
#include <cuda_bf16.h>
#include <cstdint>

// ---------------- problem-size scratch (static device globals; no allocs) ---
#define NMAX 100096
#define EMAX 1600256
#define ENMAX (NMAX + EMAX)
#define POOLB 240

__device__ int    g_not64;               // 1 if edge_index is int32
__device__ int    g_deg[NMAX];
__device__ int    g_rp[NMAX + 1];        // CSR row pointers (by SRC)
__device__ int    g_cur[NMAX];
__device__ int    g_bsum[128];
__device__ int    g_sd[ENMAX];           // dst per CSR slot (src-sorted)
__device__ float2 g_h1[NMAX * 32];       // layer1 features, interleaved (c, c+32)
__device__ float  g_g1[NMAX * 64];       // layer1 output (post relu) = layer2 input
__device__ float2 g_h2[NMAX * 32];       // layer2 features, interleaved
__device__ float  g_g2[NMAX * 64];       // layer2 output
__device__ float  g_as1[NMAX], g_ad1[NMAX];
__device__ float  g_as2[NMAX], g_ad2[NMAX];
__device__ float  g_acc[NMAX * 64];      // scatter accumulator
__device__ float  g_den[NMAX];           // softmax denominators
__device__ float  g_pool[POOLB * 64];    // pool partials

// ---------------- init ------------------------------------------------------
__global__ void k_zero(int n) {
    int i = blockIdx.x * blockDim.x + threadIdx.x;
    if (i < n) g_deg[i] = 0;
    if (i == 0) g_not64 = 0;
}

// ---------------- edge-index dtype detection --------------------------------
__global__ void k_detect(const long long* __restrict__ ei, int nq) {
    int i = blockIdx.x * blockDim.x + threadIdx.x;
    if (i < nq && ((unsigned long long)ei[i] >> 32) != 0ull) atomicOr(&g_not64, 1);
}

__device__ __forceinline__ int load_idx(const void* ei, long long pos) {
    if (g_not64) return ((const int*)ei)[pos];
    return (int)((const long long*)ei)[pos];
}

__device__ __forceinline__ int clampi(int v, int n) {
    v = v < 0 ? 0 : v;
    return v >= n ? n - 1 : v;
}

// ---------------- out-degree histogram (by SRC, incl. self loops) ------------
__global__ void k_hist(const void* __restrict__ ei, int E, int EN, int n) {
    int i = blockIdx.x * blockDim.x + threadIdx.x;
    if (i >= EN) return;
    int s = (i < E) ? clampi(load_idx(ei, i), n) : (i - E);
    atomicAdd(&g_deg[s], 1);
}

// ---------------- prefix scan -------------------------------------------------
__global__ void k_scan_block(int n) {
    __shared__ int s[1024];
    int i = blockIdx.x * 1024 + threadIdx.x;
    int v = (i < n) ? g_deg[i] : 0;
    s[threadIdx.x] = v;
    __syncthreads();
#pragma unroll
    for (int o = 1; o < 1024; o <<= 1) {
        int t = (threadIdx.x >= (unsigned)o) ? s[threadIdx.x - o] : 0;
        __syncthreads();
        s[threadIdx.x] += t;
        __syncthreads();
    }
    if (i < n) g_rp[i] = s[threadIdx.x] - v;          // exclusive within block
    if (threadIdx.x == 1023) g_bsum[blockIdx.x] = s[1023];
}

__global__ void k_scan_top(int nb) {      // one block, 128 threads, nb <= 128
    __shared__ int s[128];
    int t = threadIdx.x;
    int v = (t < nb) ? g_bsum[t] : 0;
    s[t] = v;
    __syncthreads();
#pragma unroll
    for (int o = 1; o < 128; o <<= 1) {
        int tv = (t >= (unsigned)o) ? s[t - o] : 0;
        __syncthreads();
        s[t] += tv;
        __syncthreads();
    }
    if (t < nb) g_bsum[t] = s[t] - v;                 // exclusive
}

__global__ void k_scan_add(int n, int total) {
    int i = blockIdx.x * blockDim.x + threadIdx.x;
    if (i < n) {
        int v = g_rp[i] + g_bsum[i >> 10];
        g_rp[i] = v;
        g_cur[i] = v;
    }
    if (i == 0) g_rp[n] = total;
}

// ---------------- scatter edges into src-CSR order (store dst) --------------
__global__ void k_scatter(const void* __restrict__ ei, int E, int EN, int n) {
    int i = blockIdx.x * blockDim.x + threadIdx.x;
    if (i >= EN) return;
    int s, d;
    if (i < E) {
        s = clampi(load_idx(ei, i), n);
        d = clampi(load_idx(ei, (long long)E + i), n);
    } else { s = i - E; d = s; }
    int pos = atomicAdd(&g_cur[s], 1);
    if (pos >= 0 && pos < ENMAX) g_sd[pos] = d;
}

// ---------------- GEMM + attention scalars ----------------------------------
// 256 threads, 8 warps, 2 node-rows per warp (16 rows/block).
template <int FIN>
__global__ void __launch_bounds__(256)
k_gemm(const float* __restrict__ X, const float* __restrict__ Wg,
       const float* __restrict__ att_s, const float* __restrict__ att_d,
       float2* __restrict__ H, float* __restrict__ AS, float* __restrict__ AD,
       int n) {
    __shared__ float2 Wp[FIN * 32];
    __shared__ float atts[64], attd[64];
    __shared__ __align__(16) float xs[8][2][FIN];

    int tid = threadIdx.x;
    for (int i = tid; i < FIN * 32; i += 256) {
        int k = i >> 5, c = i & 31;
        Wp[i] = make_float2(Wg[k * 64 + c], Wg[k * 64 + c + 32]);
    }
    if (tid < 64) { atts[tid] = att_s[tid]; attd[tid] = att_d[tid]; }
    __syncthreads();

    int warp = tid >> 5, lane = tid & 31;
    int stride = gridDim.x * 16;

    for (int base = (blockIdx.x * 8 + warp) * 2; base < n; base += stride) {
        int nrows = n - base;
        if (nrows > 2) nrows = 2;
        for (int r = 0; r < nrows; r++) {
            const float* xp = X + (size_t)(base + r) * FIN;
#pragma unroll
            for (int k = lane; k < FIN; k += 32) xs[warp][r][k] = xp[k];
        }
        __syncwarp();

        float a00 = 0.f, a01 = 0.f, a10 = 0.f, a11 = 0.f;
#pragma unroll
        for (int k4 = 0; k4 < FIN; k4 += 4) {
            float4 x0 = *(const float4*)&xs[warp][0][k4];
            float4 x1 = *(const float4*)&xs[warp][1][k4];
#pragma unroll
            for (int kk = 0; kk < 4; kk++) {
                float2 w = Wp[(k4 + kk) * 32 + lane];
                float x0k = (kk == 0) ? x0.x : (kk == 1) ? x0.y : (kk == 2) ? x0.z : x0.w;
                float x1k = (kk == 0) ? x1.x : (kk == 1) ? x1.y : (kk == 2) ? x1.z : x1.w;
                a00 += x0k * w.x; a01 += x0k * w.y;
                a10 += x1k * w.x; a11 += x1k * w.y;
            }
        }

#pragma unroll
        for (int r = 0; r < 2; r++) {
            if (r >= nrows) break;
            float v0 = r ? a10 : a00, v1 = r ? a11 : a01;
            H[(size_t)(base + r) * 32 + lane] = make_float2(v0, v1);
            float ps = v0 * atts[lane] + v1 * atts[lane + 32];
            float pd = v0 * attd[lane] + v1 * attd[lane + 32];
#pragma unroll
            for (int ofs = 16; ofs; ofs >>= 1) {
                ps += __shfl_xor_sync(0xffffffffu, ps, ofs);
                pd += __shfl_xor_sync(0xffffffffu, pd, ofs);
            }
            if (lane == 0) { AS[base + r] = ps; AD[base + r] = pd; }
        }
        __syncwarp();
    }
}

// ---------------- zero accumulators ------------------------------------------
__global__ void k_zeroacc(int n) {
    int total = n * 64;
    for (int i = blockIdx.x * blockDim.x + threadIdx.x; i < total;
         i += gridDim.x * blockDim.x) {
        g_acc[i] = 0.f;
        if (i < n) g_den[i] = 0.f;
    }
}

// ---------------- scatter aggregation: warp per SRC node ---------------------
// Streams h[src] once; scatters w*h into acc[dst] via REDG (no return).
__global__ void __launch_bounds__(256)
k_scatagg(const float2* __restrict__ H, const float* __restrict__ AS,
          const float* __restrict__ AD, int n) {
    int src = (blockIdx.x * blockDim.x + threadIdx.x) >> 5;
    int lane = threadIdx.x & 31;
    if (src >= n) return;

    float2 hv = H[(size_t)src * 32 + lane];   // contiguous 256B per warp
    float as_v = AS[src];
    int beg = g_rp[src], end = g_rp[src + 1];

    for (int j = beg; j < end; j++) {
        int d = g_sd[j];
        float e = as_v + AD[d];
        e = (e > 0.f) ? e : 0.2f * e;          // leaky_relu, slope 0.2
        float w = __expf(e);
        float* ap = g_acc + (size_t)d * 64;
        atomicAdd(ap + lane, w * hv.x);
        atomicAdd(ap + 32 + lane, w * hv.y);
        if (lane == 0) atomicAdd(&g_den[d], w);
    }
}

// ---------------- normalize + bias (+relu) -----------------------------------
__global__ void k_norm(const float* __restrict__ bias, float* __restrict__ OUT,
                       int n, int do_relu) {
    int total = n * 64;
    for (int i = blockIdx.x * blockDim.x + threadIdx.x; i < total;
         i += gridDim.x * blockDim.x) {
        int node = i >> 6, col = i & 63;
        float v = g_acc[i] / (g_den[node] + 1e-16f) + bias[col];
        if (do_relu) v = fmaxf(v, 0.f);
        OUT[i] = v;
    }
}

// ---------------- global mean pool (atomic-free, 2 stages) -------------------
__global__ void k_pool_a(const float* __restrict__ G, int n) {
    __shared__ float sm[256];
    int col = threadIdx.x & 63;
    int rg = threadIdx.x >> 6;   // 0..3
    float acc = 0.f;
    for (int r = blockIdx.x * 4 + rg; r < n; r += gridDim.x * 4)
        acc += G[(size_t)r * 64 + col];
    sm[threadIdx.x] = acc;
    __syncthreads();
    if (rg == 0)
        g_pool[blockIdx.x * 64 + col] =
            sm[col] + sm[64 + col] + sm[128 + col] + sm[192 + col];
}

__global__ void k_pool_b(float* __restrict__ out, int n) {
    int col = threadIdx.x;   // 64 threads
    float acc = 0.f;
    for (int b = 0; b < POOLB; b++) acc += g_pool[b * 64 + col];
    out[col] = acc * (1.0f / (float)n);
}

// ---------------- launch ----------------------------------------------------
extern "C" void kernel_launch(void* const* d_in, const int* in_sizes, int n_in,
                              void* d_out, int out_size) {
    const float* x   = (const float*)d_in[0];
    const void*  ei  = d_in[1];   // edge_index, dtype detected on device
    const float* W1  = (const float*)d_in[3];
    const float* as1 = (const float*)d_in[4];
    const float* ad1 = (const float*)d_in[5];
    const float* b1  = (const float*)d_in[6];
    const float* W2  = (const float*)d_in[7];
    const float* as2 = (const float*)d_in[8];
    const float* ad2 = (const float*)d_in[9];
    const float* b2  = (const float*)d_in[10];
    float* out = (float*)d_out;

    int n  = in_sizes[0] / 128;   // N nodes
    int E  = in_sizes[1] / 2;     // edges
    int EN = E + n;               // edges + self loops

    int gemmBlocks = (n + 15) / 16;
    int aggBlocks  = (n + 7) / 8;

    k_zero<<<(n + 255) / 256, 256>>>(n);                               // 0
    int nq = E < 2048 ? E : 2048;
    k_detect<<<(nq + 255) / 256, 256>>>((const long long*)ei, nq);     // 1
    k_hist<<<(EN + 255) / 256, 256>>>(ei, E, EN, n);                   // 2
    // Slot 3 (profiled): new-tiling gemm128 on real inputs (CSR-independent).
    k_gemm<128><<<gemmBlocks, 256>>>(x, W1, as1, ad1,
                                     g_h1, g_as1, g_ad1, n);           // 3 <- profiled
    int nb = (n + 1023) / 1024;
    k_scan_block<<<nb, 1024>>>(n);                                     // 4
    k_scan_top<<<1, 128>>>(nb);                                        // 5
    k_scan_add<<<(n + 255) / 256, 256>>>(n, EN);                       // 6
    k_scatter<<<(EN + 255) / 256, 256>>>(ei, E, EN, n);                // 7

    // --- layer 1: scatter aggregation + normalize(relu) ---
    k_zeroacc<<<480, 256>>>(n);
    k_scatagg<<<aggBlocks, 256>>>(g_h1, g_as1, g_ad1, n);
    k_norm<<<480, 256>>>(b1, g_g1, n, 1);

    // --- layer 2 ---
    k_gemm<64><<<gemmBlocks, 256>>>(g_g1, W2, as2, ad2, g_h2, g_as2, g_ad2, n);
    k_zeroacc<<<480, 256>>>(n);
    k_scatagg<<<aggBlocks, 256>>>(g_h2, g_as2, g_ad2, n);
    k_norm<<<480, 256>>>(b2, g_g2, n, 0);

    // --- global mean pool (atomic-free) ---
    k_pool_a<<<POOLB, 256>>>(g_g2, n);
    k_pool_b<<<1, 64>>>(out, n);
}